// round 9
// baseline (speedup 1.0000x reference)
#include <cuda_runtime.h>
#include <cstdint>

#define B_N   256
#define C_N   1000
#define D_N   512
#define WROWS 4000
#define RG_MAX 249              // last valid 16-row group (250 groups)

// ---------------- device scratch (no allocations allowed) ----------------
// Packed fragment-order operands (written by prep, streamed by GEMM):
// g_Wp[((r16*16 + ch)*4 + k8)*32 + lane] : float4 = {W[R+g][K+t], W[R+8+g][K+t],
//        W[R+g][K+t+4], W[R+8+g][K+t+4]},  R=16*r16, K=32ch+8k8, lane=(g<<2)|t
// g_xp (float2 view of g_xp4)[((n8*16 + ch)*4 + k8)*32 + lane] :
//        float2 = {xn[8*n8+g][K+t], xn[8*n8+g][K+t+4]}
__device__ float4 g_Wp[250 * 16 * 4 * 32];   // 8 MB
__device__ float4 g_xp4[32 * 16 * 4 * 16];   // 512 KB (float2 pairs in float4)
__device__ float  g_G[C_N * 16];
__device__ float  g_invn[C_N * 4];

// ---------------- helpers ----------------
__device__ __forceinline__ float dot4(float4 a, float4 b) {
    return a.x * b.x + a.y * b.y + a.z * b.z + a.w * b.w;
}
__device__ __forceinline__ float tf32r(float v) {
    unsigned r;
    asm("cvt.rna.tf32.f32 %0, %1;" : "=r"(r) : "f"(v));
    return __uint_as_float(r);
}
__device__ __forceinline__ float4 tf32r4(float4 v) {
    return make_float4(tf32r(v.x), tf32r(v.y), tf32r(v.z), tf32r(v.w));
}
__device__ __forceinline__ uint32_t smem_u32(const void* p) {
    uint32_t a;
    asm("{ .reg .u64 t; cvta.to.shared.u64 t, %1; cvt.u32.u64 %0, t; }" : "=r"(a) : "l"(p));
    return a;
}
__device__ __forceinline__ void cp16(uint32_t dst, const void* src) {
    asm volatile("cp.async.cg.shared.global [%0], [%1], 16;" :: "r"(dst), "l"(src));
}
__device__ __forceinline__ void mma_tf32(float* d, const uint32_t* a, const uint32_t* b) {
    asm volatile(
        "mma.sync.aligned.m16n8k8.row.col.f32.tf32.tf32.f32 "
        "{%0,%1,%2,%3}, {%4,%5,%6,%7}, {%8,%9}, {%0,%1,%2,%3};"
        : "+f"(d[0]), "+f"(d[1]), "+f"(d[2]), "+f"(d[3])
        : "r"(a[0]), "r"(a[1]), "r"(a[2]), "r"(a[3]), "r"(b[0]), "r"(b[1]));
}

// ---------------------------------------------------------------------------
// Prep: blocks [0,32): normalize 8 x-rows, pack to g_xp.
//       blocks [32,282): 16 W-rows (4 classes): Gram+invnorm (raw fp32),
//       tf32-round + pack to g_Wp.
// ---------------------------------------------------------------------------
__global__ __launch_bounds__(256) void prep_kernel(const float* __restrict__ x,
                                                   const float* __restrict__ W) {
    __shared__ float tile[16][516];
    const int tid = threadIdx.x, lane = tid & 31, w = tid >> 5;

    if (blockIdx.x < 32) {
        const int n8 = blockIdx.x;          // 8-row group of x
        const int row = n8 * 8 + w;         // warp w: one row (w always < 8)
        {
            const float4* xr = reinterpret_cast<const float4*>(x + (size_t)row * D_N);
            float4 v[4]; float ss = 0.f;
            #pragma unroll
            for (int i = 0; i < 4; i++) { v[i] = xr[lane + 32 * i]; ss += dot4(v[i], v[i]); }
            #pragma unroll
            for (int o = 16; o > 0; o >>= 1) ss += __shfl_xor_sync(0xffffffffu, ss, o);
            float inv = 1.0f / fmaxf(sqrtf(ss), 1e-12f);
            #pragma unroll
            for (int i = 0; i < 4; i++) {
                float4 s = tf32r4(make_float4(v[i].x*inv, v[i].y*inv, v[i].z*inv, v[i].w*inv));
                int col = 4 * lane + 128 * i;
                tile[w][col] = s.x; tile[w][col+1] = s.y;
                tile[w][col+2] = s.z; tile[w][col+3] = s.w;
            }
        }
        __syncthreads();
        float2* xp = reinterpret_cast<float2*>(g_xp4);
        #pragma unroll
        for (int j = 0; j < 8; j++) {
            int idx = j * 256 + tid;                  // 2048 float2
            int ch = idx >> 7, k8 = (idx >> 5) & 3, l = idx & 31;
            int g = l >> 2, t = l & 3;
            int col = ch * 32 + k8 * 8 + t;
            xp[((n8 * 16 + ch) * 4 + k8) * 32 + l] =
                make_float2(tile[g][col], tile[g][col + 4]);
        }
    } else {
        const int r16 = blockIdx.x - 32;            // 16-wrow group = 4 classes
        const int wr0 = r16 * 16;
        // stage tf32-rounded rows to smem (coalesced float4)
        const float4* W4 = reinterpret_cast<const float4*>(W);
        #pragma unroll
        for (int j = 0; j < 8; j++) {
            int idx = j * 256 + tid;                 // 2048 float4
            int r = idx >> 7, q = idx & 127;
            float4 v = tf32r4(W4[(size_t)(wr0 + r) * 128 + q]);
            *reinterpret_cast<float4*>(&tile[r][q * 4]) = v;
        }
        __syncthreads();
        // Gram from RAW W: warp w<4 handles class c = 4*r16 + w
        if (w < 4) {
            const int c = 4 * r16 + w;
            const float4* wr = reinterpret_cast<const float4*>(W + (size_t)c * 4 * D_N);
            float4 ra[4][4];
            #pragma unroll
            for (int r = 0; r < 4; r++)
                #pragma unroll
                for (int i = 0; i < 4; i++)
                    ra[r][i] = wr[r * 128 + lane * 4 + i];
            float p[10];
            #pragma unroll
            for (int i = 0; i < 10; i++) p[i] = 0.f;
            #pragma unroll
            for (int i = 0; i < 4; i++) {
                p[0] += dot4(ra[0][i], ra[0][i]); p[1] += dot4(ra[0][i], ra[1][i]);
                p[2] += dot4(ra[0][i], ra[2][i]); p[3] += dot4(ra[0][i], ra[3][i]);
                p[4] += dot4(ra[1][i], ra[1][i]); p[5] += dot4(ra[1][i], ra[2][i]);
                p[6] += dot4(ra[1][i], ra[3][i]); p[7] += dot4(ra[2][i], ra[2][i]);
                p[8] += dot4(ra[2][i], ra[3][i]); p[9] += dot4(ra[3][i], ra[3][i]);
            }
            #pragma unroll
            for (int o = 16; o > 0; o >>= 1)
                #pragma unroll
                for (int i = 0; i < 10; i++) p[i] += __shfl_xor_sync(0xffffffffu, p[i], o);
            if (lane == 0) {
                float inv[4];
                inv[0] = 1.0f / fmaxf(sqrtf(p[0]), 1e-12f);
                inv[1] = 1.0f / fmaxf(sqrtf(p[4]), 1e-12f);
                inv[2] = 1.0f / fmaxf(sqrtf(p[7]), 1e-12f);
                inv[3] = 1.0f / fmaxf(sqrtf(p[9]), 1e-12f);
                #pragma unroll
                for (int s = 0; s < 4; s++) g_invn[c * 4 + s] = inv[s];
                const int pidx[4][4] = {{0,1,2,3},{1,4,5,6},{2,5,7,8},{3,6,8,9}};
                #pragma unroll
                for (int s = 0; s < 4; s++)
                    #pragma unroll
                    for (int t = 0; t < 4; t++)
                        g_G[c * 16 + s * 4 + t] = p[pidx[s][t]] * inv[s] * inv[t];
            }
        }
        // pack A fragments
        #pragma unroll
        for (int j = 0; j < 8; j++) {
            int idx = j * 256 + tid;                 // 2048 float4
            int ch = idx >> 7, k8 = (idx >> 5) & 3, l = idx & 31;
            int g = l >> 2, t = l & 3;
            int col = ch * 32 + k8 * 8 + t;
            g_Wp[((r16 * 16 + ch) * 4 + k8) * 32 + l] =
                make_float4(tile[g][col], tile[g + 8][col],
                            tile[g][col + 4], tile[g + 8][col + 4]);
        }
    }
}

// ---------------------------------------------------------------------------
// GEMM: 64 wrows x 64 b per CTA, 256 threads (8 warps, warpgrid 2x4, warp
// tile 32x16). 3-stage cp.async pipeline, packed-fragment smem (A: LDS.128,
// B: LDS.64, conflict-free). Fused Gram epilogue.
// ---------------------------------------------------------------------------
#define STG_F  4096                 // floats per stage (A 2048 + B 2048) = 16 KB
#define CP     67                   // C-tile pitch (odd -> scalar stores only)

__global__ __launch_bounds__(256, 2) void gemm_epi_kernel(float* __restrict__ out) {
    extern __shared__ float sm[];
    const int tid = threadIdx.x, wid = tid >> 5, lane = tid & 31;
    const int m_sel = wid & 1, n_sel = wid >> 1;      // 2 (M) x 4 (N)
    const int rg0 = blockIdx.x * 4;       // 16-row groups
    const int ng0 = blockIdx.y * 8;       // 8-col groups
    const int b0 = blockIdx.y * 64;

    float acc[2][2][4];
    #pragma unroll
    for (int mi = 0; mi < 2; mi++)
        #pragma unroll
        for (int nj = 0; nj < 2; nj++)
            #pragma unroll
            for (int q = 0; q < 4; q++) acc[mi][nj][q] = 0.f;

    const uint32_t sbase = smem_u32(sm);
    const float2* xp = reinterpret_cast<const float2*>(g_xp4);

    auto load = [&](int ch, int st) {
        const uint32_t Ab = sbase + st * (STG_F * 4);
        const uint32_t Bb = Ab + 2048 * 4;
        #pragma unroll
        for (int i = 0; i < 2; i++) {                 // A: 512 float4
            int f = i * 256 + tid;
            int grp = f >> 7, k8 = (f >> 5) & 3, l = f & 31;
            int gg = rg0 + grp; if (gg > RG_MAX) gg = RG_MAX;
            cp16(Ab + f * 16, g_Wp + ((gg * 16 + ch) * 4 + k8) * 32 + l);
        }
        #pragma unroll
        for (int i = 0; i < 2; i++) {                 // B: 512 x 16B (1024 float2)
            int f = i * 256 + tid;
            int grp = f >> 6, k8 = (f >> 4) & 3, lp = (f & 15) * 2;
            cp16(Bb + f * 16, xp + (((ng0 + grp) * 16 + ch) * 4 + k8) * 32 + lp);
        }
        asm volatile("cp.async.commit_group;" ::: "memory");
    };

    load(0, 0);
    load(1, 1);
    #pragma unroll
    for (int ch = 0; ch < 16; ch++) {
        if (ch < 15) asm volatile("cp.async.wait_group 1;" ::: "memory");
        else         asm volatile("cp.async.wait_group 0;" ::: "memory");
        __syncthreads();
        if (ch + 2 < 16) load(ch + 2, (ch + 2) % 3);
        const float* As = sm + (ch % 3) * STG_F;
        const float* Bs = As + 2048;
        #pragma unroll
        for (int k8 = 0; k8 < 4; k8++) {
            float4 afv[2]; float2 bfv[2];
            #pragma unroll
            for (int mi = 0; mi < 2; mi++) {
                int grp = m_sel * 2 + mi;
                afv[mi] = *reinterpret_cast<const float4*>(
                    As + ((grp * 4 + k8) * 32 + lane) * 4);
            }
            #pragma unroll
            for (int nj = 0; nj < 2; nj++) {
                int grp = n_sel * 2 + nj;
                bfv[nj] = *reinterpret_cast<const float2*>(
                    Bs + ((grp * 4 + k8) * 32 + lane) * 2);
            }
            #pragma unroll
            for (int mi = 0; mi < 2; mi++)
                #pragma unroll
                for (int nj = 0; nj < 2; nj++)
                    mma_tf32(acc[mi][nj],
                             reinterpret_cast<const uint32_t*>(&afv[mi]),
                             reinterpret_cast<const uint32_t*>(&bfv[nj]));
        }
    }
    __syncthreads();

    // ---- C dump (64 x 64, scalar stores, odd pitch) ----
    float* Cs = sm;
    {
        const int g = lane >> 2, t = lane & 3;
        #pragma unroll
        for (int mi = 0; mi < 2; mi++)
            #pragma unroll
            for (int nj = 0; nj < 2; nj++) {
                int r = m_sel * 32 + 16 * mi + g;
                int c = n_sel * 16 + 8 * nj + 2 * t;
                Cs[r * CP + c]           = acc[mi][nj][0];
                Cs[r * CP + c + 1]       = acc[mi][nj][1];
                Cs[(r + 8) * CP + c]     = acc[mi][nj][2];
                Cs[(r + 8) * CP + c + 1] = acc[mi][nj][3];
            }
    }
    __syncthreads();

    // ---- fused epilogue: 16 classes x 16 b-threads, 4 b-values each ----
    const int cc = tid & 15, bb = tid >> 4;
    const int cg = blockIdx.x * 16 + cc;
    if (cg < C_N) {
        float inv[4], Gm[16];
        #pragma unroll
        for (int s = 0; s < 4; s++) inv[s] = g_invn[cg * 4 + s];
        #pragma unroll
        for (int t = 0; t < 16; t++) Gm[t] = g_G[cg * 16 + t];
        #pragma unroll
        for (int i = 0; i < 4; i++) {
            int b = bb + 16 * i;
            float l[4];
            #pragma unroll
            for (int s = 0; s < 4; s++)
                l[s] = Cs[(4 * cc + s) * CP + b] * inv[s];
            float num = l[0]*l[0] + l[1]*l[1] + l[2]*l[2] + l[3]*l[3];
            float den2 = 0.f;
            #pragma unroll
            for (int s = 0; s < 4; s++)
                #pragma unroll
                for (int t = 0; t < 4; t++)
                    den2 += l[s] * l[t] * Gm[s * 4 + t];
            out[(size_t)(b0 + b) * C_N + cg] =
                num / fmaxf(sqrtf(fmaxf(den2, 0.f)), 1e-12f);
        }
    }
}

// ---------------------------------------------------------------------------
extern "C" void kernel_launch(void* const* d_in, const int* in_sizes, int n_in,
                              void* d_out, int out_size) {
    const float* x = (const float*)d_in[0];   // [256, 512]
    const float* W = (const float*)d_in[1];   // [1000, 4, 512]
    float* out = (float*)d_out;               // [256, 1000]

    cudaFuncSetAttribute(gemm_epi_kernel,
                         cudaFuncAttributeMaxDynamicSharedMemorySize, 3 * STG_F * 4);
    prep_kernel<<<282, 256>>>(x, W);
    gemm_epi_kernel<<<dim3(63, 4), 256, 3 * STG_F * 4>>>(out);
}

// round 10
// speedup vs baseline: 1.1490x; 1.1490x over previous
#include <cuda_runtime.h>
#include <cstdint>

#define B_N   256
#define C_N   1000
#define D_N   512
#define WROWS 4000
#define RG_MAX 249              // last valid 16-row group (250 groups)

// ---------------- device scratch (no allocations allowed) ----------------
// Packed fragment-order operands (written by prep, streamed by GEMM):
// g_Wp[(gg*64 + kk)*32 + lane] : float4 A-frag {W[R+g][K+t], W[R+8+g][K+t],
//        W[R+g][K+t+4], W[R+8+g][K+t+4]}, R=16*gg, K=8*kk, lane=(g<<2)|t
// g_xp (float2 view)[(n8*64 + kk)*32 + lane] : float2 B-frag
//        {xn[8*n8+g][K+t], xn[8*n8+g][K+t+4]}
__device__ float4 g_Wp[250 * 16 * 4 * 32];   // 8 MB
__device__ float4 g_xp4[32 * 16 * 4 * 16];   // 512 KB (float2 pairs in float4)
__device__ float  g_G[C_N * 16];
__device__ float  g_invn[C_N * 4];

// ---------------- helpers ----------------
__device__ __forceinline__ float dot4(float4 a, float4 b) {
    return a.x * b.x + a.y * b.y + a.z * b.z + a.w * b.w;
}
__device__ __forceinline__ float tf32r(float v) {
    unsigned r;
    asm("cvt.rna.tf32.f32 %0, %1;" : "=r"(r) : "f"(v));
    return __uint_as_float(r);
}
__device__ __forceinline__ float4 tf32r4(float4 v) {
    return make_float4(tf32r(v.x), tf32r(v.y), tf32r(v.z), tf32r(v.w));
}
__device__ __forceinline__ void mma_tf32(float* d, const uint32_t* a, const uint32_t* b) {
    asm volatile(
        "mma.sync.aligned.m16n8k8.row.col.f32.tf32.tf32.f32 "
        "{%0,%1,%2,%3}, {%4,%5,%6,%7}, {%8,%9}, {%0,%1,%2,%3};"
        : "+f"(d[0]), "+f"(d[1]), "+f"(d[2]), "+f"(d[3])
        : "r"(a[0]), "r"(a[1]), "r"(a[2]), "r"(a[3]), "r"(b[0]), "r"(b[1]));
}

// ---------------------------------------------------------------------------
// Prep: blocks [0,32): normalize 8 x-rows, pack to g_xp.
//       blocks [32,282): 16 W-rows (4 classes): Gram+invnorm (raw fp32),
//       tf32-round + pack to g_Wp.
// ---------------------------------------------------------------------------
__global__ __launch_bounds__(256) void prep_kernel(const float* __restrict__ x,
                                                   const float* __restrict__ W) {
    __shared__ float tile[16][516];
    const int tid = threadIdx.x, lane = tid & 31, w = tid >> 5;

    if (blockIdx.x < 32) {
        const int n8 = blockIdx.x;          // 8-row group of x
        const int row = n8 * 8 + w;         // warp w: one row (w always < 8)
        {
            const float4* xr = reinterpret_cast<const float4*>(x + (size_t)row * D_N);
            float4 v[4]; float ss = 0.f;
            #pragma unroll
            for (int i = 0; i < 4; i++) { v[i] = xr[lane + 32 * i]; ss += dot4(v[i], v[i]); }
            #pragma unroll
            for (int o = 16; o > 0; o >>= 1) ss += __shfl_xor_sync(0xffffffffu, ss, o);
            float inv = 1.0f / fmaxf(sqrtf(ss), 1e-12f);
            #pragma unroll
            for (int i = 0; i < 4; i++) {
                float4 s = tf32r4(make_float4(v[i].x*inv, v[i].y*inv, v[i].z*inv, v[i].w*inv));
                int col = 4 * lane + 128 * i;
                tile[w][col] = s.x; tile[w][col+1] = s.y;
                tile[w][col+2] = s.z; tile[w][col+3] = s.w;
            }
        }
        __syncthreads();
        float2* xp = reinterpret_cast<float2*>(g_xp4);
        #pragma unroll
        for (int j = 0; j < 8; j++) {
            int idx = j * 256 + tid;                  // 2048 float2
            int ch = idx >> 7, k8 = (idx >> 5) & 3, l = idx & 31;
            int g = l >> 2, t = l & 3;
            int col = ch * 32 + k8 * 8 + t;
            xp[((n8 * 16 + ch) * 4 + k8) * 32 + l] =
                make_float2(tile[g][col], tile[g][col + 4]);
        }
    } else {
        const int r16 = blockIdx.x - 32;            // 16-wrow group = 4 classes
        const int wr0 = r16 * 16;
        const float4* W4 = reinterpret_cast<const float4*>(W);
        #pragma unroll
        for (int j = 0; j < 8; j++) {
            int idx = j * 256 + tid;                 // 2048 float4
            int r = idx >> 7, q = idx & 127;
            float4 v = tf32r4(W4[(size_t)(wr0 + r) * 128 + q]);
            *reinterpret_cast<float4*>(&tile[r][q * 4]) = v;
        }
        __syncthreads();
        // Gram from RAW W: warp w<4 handles class c = 4*r16 + w
        if (w < 4) {
            const int c = 4 * r16 + w;
            const float4* wr = reinterpret_cast<const float4*>(W + (size_t)c * 4 * D_N);
            float4 ra[4][4];
            #pragma unroll
            for (int r = 0; r < 4; r++)
                #pragma unroll
                for (int i = 0; i < 4; i++)
                    ra[r][i] = wr[r * 128 + lane * 4 + i];
            float p[10];
            #pragma unroll
            for (int i = 0; i < 10; i++) p[i] = 0.f;
            #pragma unroll
            for (int i = 0; i < 4; i++) {
                p[0] += dot4(ra[0][i], ra[0][i]); p[1] += dot4(ra[0][i], ra[1][i]);
                p[2] += dot4(ra[0][i], ra[2][i]); p[3] += dot4(ra[0][i], ra[3][i]);
                p[4] += dot4(ra[1][i], ra[1][i]); p[5] += dot4(ra[1][i], ra[2][i]);
                p[6] += dot4(ra[1][i], ra[3][i]); p[7] += dot4(ra[2][i], ra[2][i]);
                p[8] += dot4(ra[2][i], ra[3][i]); p[9] += dot4(ra[3][i], ra[3][i]);
            }
            #pragma unroll
            for (int o = 16; o > 0; o >>= 1)
                #pragma unroll
                for (int i = 0; i < 10; i++) p[i] += __shfl_xor_sync(0xffffffffu, p[i], o);
            if (lane == 0) {
                float inv[4];
                inv[0] = 1.0f / fmaxf(sqrtf(p[0]), 1e-12f);
                inv[1] = 1.0f / fmaxf(sqrtf(p[4]), 1e-12f);
                inv[2] = 1.0f / fmaxf(sqrtf(p[7]), 1e-12f);
                inv[3] = 1.0f / fmaxf(sqrtf(p[9]), 1e-12f);
                #pragma unroll
                for (int s = 0; s < 4; s++) g_invn[c * 4 + s] = inv[s];
                const int pidx[4][4] = {{0,1,2,3},{1,4,5,6},{2,5,7,8},{3,6,8,9}};
                #pragma unroll
                for (int s = 0; s < 4; s++)
                    #pragma unroll
                    for (int t = 0; t < 4; t++)
                        g_G[c * 16 + s * 4 + t] = p[pidx[s][t]] * inv[s] * inv[t];
            }
        }
        // pack A fragments
        #pragma unroll
        for (int j = 0; j < 8; j++) {
            int idx = j * 256 + tid;                 // 2048 float4
            int ch = idx >> 7, k8 = (idx >> 5) & 3, l = idx & 31;
            int g = l >> 2, t = l & 3;
            int col = ch * 32 + k8 * 8 + t;
            g_Wp[((r16 * 16 + ch) * 4 + k8) * 32 + l] =
                make_float4(tile[g][col], tile[g + 8][col],
                            tile[g][col + 4], tile[g + 8][col + 4]);
        }
    }
}

// ---------------------------------------------------------------------------
// GEMM: direct-LDG mainloop — NO smem staging, NO barriers. 64x64 CTA tile,
// 4 warps (warpgrid 2x2, warp tile 32x32). Each warp LDGs its fragments
// straight from the packed global layout (coalesced; L1 dedups the 2-way
// duplication). Fully unrolled kk=0..63 so ptxas batches LDGs for MLP.
// Fused Gram epilogue via a small static-smem C tile.
// ---------------------------------------------------------------------------
#define CP 67                       // C-tile pitch (odd -> scalar stores only)

__global__ __launch_bounds__(128, 2) void gemm_epi_kernel(float* __restrict__ out) {
    __shared__ float Cs[64 * CP];   // ~17 KB
    const int tid = threadIdx.x, wid = tid >> 5, lane = tid & 31;
    const int m_sel = wid & 1, n_sel = wid >> 1;      // 2 (M) x 2 (N)
    const int rg0 = blockIdx.x * 4;       // 16-row groups
    const int ng0 = blockIdx.y * 8;       // 8-col groups
    const int b0  = blockIdx.y * 64;

    float acc[2][4][4];
    #pragma unroll
    for (int mi = 0; mi < 2; mi++)
        #pragma unroll
        for (int nj = 0; nj < 4; nj++)
            #pragma unroll
            for (int q = 0; q < 4; q++) acc[mi][nj][q] = 0.f;

    int gg0 = rg0 + m_sel * 2;     if (gg0 > RG_MAX) gg0 = RG_MAX;
    int gg1 = rg0 + m_sel * 2 + 1; if (gg1 > RG_MAX) gg1 = RG_MAX;
    const float4* A0 = g_Wp + (size_t)gg0 * 2048 + lane;   // 64 kk * 32 lanes
    const float4* A1 = g_Wp + (size_t)gg1 * 2048 + lane;
    const float2* xp = reinterpret_cast<const float2*>(g_xp4);
    const float2* Bp0 = xp + (size_t)(ng0 + n_sel * 4 + 0) * 2048 + lane;
    const float2* Bp1 = xp + (size_t)(ng0 + n_sel * 4 + 1) * 2048 + lane;
    const float2* Bp2 = xp + (size_t)(ng0 + n_sel * 4 + 2) * 2048 + lane;
    const float2* Bp3 = xp + (size_t)(ng0 + n_sel * 4 + 3) * 2048 + lane;

    #pragma unroll
    for (int kk = 0; kk < 64; kk++) {
        float4 a[2]; float2 b[4];
        a[0] = __ldg(A0 + kk * 32);
        a[1] = __ldg(A1 + kk * 32);
        b[0] = __ldg(Bp0 + kk * 32);
        b[1] = __ldg(Bp1 + kk * 32);
        b[2] = __ldg(Bp2 + kk * 32);
        b[3] = __ldg(Bp3 + kk * 32);
        #pragma unroll
        for (int mi = 0; mi < 2; mi++)
            #pragma unroll
            for (int nj = 0; nj < 4; nj++)
                mma_tf32(acc[mi][nj],
                         reinterpret_cast<const uint32_t*>(&a[mi]),
                         reinterpret_cast<const uint32_t*>(&b[nj]));
    }

    // ---- C dump (64 x 64, scalar stores, odd pitch) ----
    {
        const int g = lane >> 2, t = lane & 3;
        #pragma unroll
        for (int mi = 0; mi < 2; mi++)
            #pragma unroll
            for (int nj = 0; nj < 4; nj++) {
                int r = m_sel * 32 + 16 * mi + g;
                int c = n_sel * 32 + 8 * nj + 2 * t;
                Cs[r * CP + c]           = acc[mi][nj][0];
                Cs[r * CP + c + 1]       = acc[mi][nj][1];
                Cs[(r + 8) * CP + c]     = acc[mi][nj][2];
                Cs[(r + 8) * CP + c + 1] = acc[mi][nj][3];
            }
    }
    __syncthreads();

    // ---- fused epilogue: 16 classes x 8 b-threads, 8 b-values each ----
    const int cc = tid & 15, bb = tid >> 4;
    const int cg = blockIdx.x * 16 + cc;
    if (cg < C_N) {
        float inv[4], Gm[16];
        #pragma unroll
        for (int s = 0; s < 4; s++) inv[s] = g_invn[cg * 4 + s];
        #pragma unroll
        for (int t = 0; t < 16; t++) Gm[t] = g_G[cg * 16 + t];
        #pragma unroll
        for (int i = 0; i < 8; i++) {
            int b = bb + 8 * i;
            float l[4];
            #pragma unroll
            for (int s = 0; s < 4; s++)
                l[s] = Cs[(4 * cc + s) * CP + b] * inv[s];
            float num = l[0]*l[0] + l[1]*l[1] + l[2]*l[2] + l[3]*l[3];
            float den2 = 0.f;
            #pragma unroll
            for (int s = 0; s < 4; s++)
                #pragma unroll
                for (int t = 0; t < 4; t++)
                    den2 += l[s] * l[t] * Gm[s * 4 + t];
            out[(size_t)(b0 + b) * C_N + cg] =
                num / fmaxf(sqrtf(fmaxf(den2, 0.f)), 1e-12f);
        }
    }
}

// ---------------------------------------------------------------------------
extern "C" void kernel_launch(void* const* d_in, const int* in_sizes, int n_in,
                              void* d_out, int out_size) {
    const float* x = (const float*)d_in[0];   // [256, 512]
    const float* W = (const float*)d_in[1];   // [1000, 4, 512]
    float* out = (float*)d_out;               // [256, 1000]

    prep_kernel<<<282, 256>>>(x, W);
    gemm_epi_kernel<<<dim3(63, 4), 128>>>(out);
}

// round 11
// speedup vs baseline: 1.3287x; 1.1563x over previous
#include <cuda_runtime.h>
#include <cuda_fp16.h>
#include <cstdint>

#define B_N   256
#define C_N   1000
#define D_N   512
#define WROWS 4000
#define RG_MAX 249              // last valid 16-row group (250 groups)

// ---------------- device scratch (no allocations allowed) ----------------
// fp16 fragment-packed operands for mma.m16n8k16.row.col:
// g_Wh[(gg*32 + kk)*32 + lane] (uint4, lane=(g<<2)|t, K=16*kk, R=16*gg):
//   { h2(W[R+g][K+2t],W[R+g][K+2t+1]), h2(W[R+8+g][K+2t],W[R+8+g][K+2t+1]),
//     h2(W[R+g][K+8+2t],...+1),        h2(W[R+8+g][K+8+2t],...+1) }
// g_xh[(n8*32 + kk)*32 + lane] (uint2, N0=8*n8):
//   { h2(xn[N0+g][K+2t],xn[N0+g][K+2t+1]), h2(xn[N0+g][K+8+2t],...+1) }
__device__ uint4 g_Wh[250 * 32 * 32];   // 4 MB
__device__ uint2 g_xh[32 * 32 * 32];    // 256 KB
__device__ float g_G[C_N * 16];
__device__ float g_invn[C_N * 4];

// ---------------- helpers ----------------
__device__ __forceinline__ float dot4(float4 a, float4 b) {
    return a.x * b.x + a.y * b.y + a.z * b.z + a.w * b.w;
}
__device__ __forceinline__ uint32_t h2(float lo, float hi) {
    __half2 h = __floats2half2_rn(lo, hi);
    return *reinterpret_cast<uint32_t*>(&h);
}
__device__ __forceinline__ void mma_f16(float* d, const uint32_t* a, const uint32_t* b) {
    asm volatile(
        "mma.sync.aligned.m16n8k16.row.col.f32.f16.f16.f32 "
        "{%0,%1,%2,%3}, {%4,%5,%6,%7}, {%8,%9}, {%0,%1,%2,%3};"
        : "+f"(d[0]), "+f"(d[1]), "+f"(d[2]), "+f"(d[3])
        : "r"(a[0]), "r"(a[1]), "r"(a[2]), "r"(a[3]), "r"(b[0]), "r"(b[1]));
}

// ---------------------------------------------------------------------------
// Prep: blocks [0,32): normalize 8 x-rows (fp32), pack fp16 frags to g_xh.
//       blocks [32,282): 16 W-rows (4 classes): Gram+invnorm (raw fp32),
//       pack fp16 frags to g_Wh.
// ---------------------------------------------------------------------------
__global__ __launch_bounds__(256) void prep_kernel(const float* __restrict__ x,
                                                   const float* __restrict__ W) {
    __shared__ float tile[16][516];
    const int tid = threadIdx.x, lane = tid & 31, w = tid >> 5;

    if (blockIdx.x < 32) {
        const int n8 = blockIdx.x;          // 8-row group of x
        const int row = n8 * 8 + w;         // warp w (always < 8): one row
        {
            const float4* xr = reinterpret_cast<const float4*>(x + (size_t)row * D_N);
            float4 v[4]; float ss = 0.f;
            #pragma unroll
            for (int i = 0; i < 4; i++) { v[i] = xr[lane + 32 * i]; ss += dot4(v[i], v[i]); }
            #pragma unroll
            for (int o = 16; o > 0; o >>= 1) ss += __shfl_xor_sync(0xffffffffu, ss, o);
            float inv = 1.0f / fmaxf(sqrtf(ss), 1e-12f);
            #pragma unroll
            for (int i = 0; i < 4; i++) {
                int col = 4 * lane + 128 * i;
                tile[w][col]     = v[i].x * inv;
                tile[w][col + 1] = v[i].y * inv;
                tile[w][col + 2] = v[i].z * inv;
                tile[w][col + 3] = v[i].w * inv;
            }
        }
        __syncthreads();
        #pragma unroll
        for (int j = 0; j < 4; j++) {
            int idx = j * 256 + tid;                  // 1024 uint2
            int kk = idx >> 5, l = idx & 31;
            int g = l >> 2, t2 = (l & 3) * 2;
            int K = kk * 16;
            g_xh[((size_t)n8 * 32 + kk) * 32 + l] = make_uint2(
                h2(tile[g][K + t2],     tile[g][K + t2 + 1]),
                h2(tile[g][K + 8 + t2], tile[g][K + 8 + t2 + 1]));
        }
    } else {
        const int r16 = blockIdx.x - 32;            // 16-wrow group = 4 classes
        const int wr0 = r16 * 16;
        const float4* W4 = reinterpret_cast<const float4*>(W);
        #pragma unroll
        for (int j = 0; j < 8; j++) {
            int idx = j * 256 + tid;                 // 2048 float4
            int r = idx >> 7, q = idx & 127;
            float4 v = W4[(size_t)(wr0 + r) * 128 + q];
            *reinterpret_cast<float4*>(&tile[r][q * 4]) = v;
        }
        __syncthreads();
        // Gram from RAW W: warp w<4 handles class c = 4*r16 + w
        if (w < 4) {
            const int c = 4 * r16 + w;
            const float4* wr = reinterpret_cast<const float4*>(W + (size_t)c * 4 * D_N);
            float4 ra[4][4];
            #pragma unroll
            for (int r = 0; r < 4; r++)
                #pragma unroll
                for (int i = 0; i < 4; i++)
                    ra[r][i] = wr[r * 128 + lane * 4 + i];
            float p[10];
            #pragma unroll
            for (int i = 0; i < 10; i++) p[i] = 0.f;
            #pragma unroll
            for (int i = 0; i < 4; i++) {
                p[0] += dot4(ra[0][i], ra[0][i]); p[1] += dot4(ra[0][i], ra[1][i]);
                p[2] += dot4(ra[0][i], ra[2][i]); p[3] += dot4(ra[0][i], ra[3][i]);
                p[4] += dot4(ra[1][i], ra[1][i]); p[5] += dot4(ra[1][i], ra[2][i]);
                p[6] += dot4(ra[1][i], ra[3][i]); p[7] += dot4(ra[2][i], ra[2][i]);
                p[8] += dot4(ra[2][i], ra[3][i]); p[9] += dot4(ra[3][i], ra[3][i]);
            }
            #pragma unroll
            for (int o = 16; o > 0; o >>= 1)
                #pragma unroll
                for (int i = 0; i < 10; i++) p[i] += __shfl_xor_sync(0xffffffffu, p[i], o);
            if (lane == 0) {
                float inv[4];
                inv[0] = 1.0f / fmaxf(sqrtf(p[0]), 1e-12f);
                inv[1] = 1.0f / fmaxf(sqrtf(p[4]), 1e-12f);
                inv[2] = 1.0f / fmaxf(sqrtf(p[7]), 1e-12f);
                inv[3] = 1.0f / fmaxf(sqrtf(p[9]), 1e-12f);
                #pragma unroll
                for (int s = 0; s < 4; s++) g_invn[c * 4 + s] = inv[s];
                const int pidx[4][4] = {{0,1,2,3},{1,4,5,6},{2,5,7,8},{3,6,8,9}};
                #pragma unroll
                for (int s = 0; s < 4; s++)
                    #pragma unroll
                    for (int t = 0; t < 4; t++)
                        g_G[c * 16 + s * 4 + t] = p[pidx[s][t]] * inv[s] * inv[t];
            }
        }
        // pack A fragments (fp16)
        #pragma unroll
        for (int j = 0; j < 4; j++) {
            int idx = j * 256 + tid;                 // 1024 uint4
            int kk = idx >> 5, l = idx & 31;
            int g = l >> 2, t2 = (l & 3) * 2;
            int K = kk * 16;
            g_Wh[((size_t)r16 * 32 + kk) * 32 + l] = make_uint4(
                h2(tile[g][K + t2],         tile[g][K + t2 + 1]),
                h2(tile[g + 8][K + t2],     tile[g + 8][K + t2 + 1]),
                h2(tile[g][K + 8 + t2],     tile[g][K + 8 + t2 + 1]),
                h2(tile[g + 8][K + 8 + t2], tile[g + 8][K + 8 + t2 + 1]));
        }
    }
}

// ---------------------------------------------------------------------------
// GEMM: direct-LDG fp16 mainloop — no smem staging, no mainloop barriers.
// 64x64 CTA tile, 4 warps (warpgrid 2x2, warp tile 32x32), K=512 in 32
// m16n8k16 steps, fully unrolled. Fused Gram epilogue.
// ---------------------------------------------------------------------------
#define CP 67                       // C-tile pitch (odd -> scalar stores only)

__global__ __launch_bounds__(128, 2) void gemm_epi_kernel(float* __restrict__ out) {
    __shared__ float Cs[64 * CP];   // ~17 KB
    const int tid = threadIdx.x, wid = tid >> 5, lane = tid & 31;
    const int m_sel = wid & 1, n_sel = wid >> 1;      // 2 (M) x 2 (N)
    const int rg0 = blockIdx.x * 4;       // 16-row groups
    const int ng0 = blockIdx.y * 8;       // 8-col groups
    const int b0  = blockIdx.y * 64;

    float acc[2][4][4];
    #pragma unroll
    for (int mi = 0; mi < 2; mi++)
        #pragma unroll
        for (int nj = 0; nj < 4; nj++)
            #pragma unroll
            for (int q = 0; q < 4; q++) acc[mi][nj][q] = 0.f;

    int gg0 = rg0 + m_sel * 2;     if (gg0 > RG_MAX) gg0 = RG_MAX;
    int gg1 = rg0 + m_sel * 2 + 1; if (gg1 > RG_MAX) gg1 = RG_MAX;
    const uint4* A0 = g_Wh + (size_t)gg0 * 1024 + lane;   // 32 kk * 32 lanes
    const uint4* A1 = g_Wh + (size_t)gg1 * 1024 + lane;
    const uint2* B0 = g_xh + (size_t)(ng0 + n_sel * 4 + 0) * 1024 + lane;
    const uint2* B1 = g_xh + (size_t)(ng0 + n_sel * 4 + 1) * 1024 + lane;
    const uint2* B2 = g_xh + (size_t)(ng0 + n_sel * 4 + 2) * 1024 + lane;
    const uint2* B3 = g_xh + (size_t)(ng0 + n_sel * 4 + 3) * 1024 + lane;

    #pragma unroll
    for (int kk = 0; kk < 32; kk++) {
        uint4 a[2]; uint2 b[4];
        a[0] = __ldg(A0 + kk * 32);
        a[1] = __ldg(A1 + kk * 32);
        b[0] = __ldg(B0 + kk * 32);
        b[1] = __ldg(B1 + kk * 32);
        b[2] = __ldg(B2 + kk * 32);
        b[3] = __ldg(B3 + kk * 32);
        #pragma unroll
        for (int mi = 0; mi < 2; mi++)
            #pragma unroll
            for (int nj = 0; nj < 4; nj++)
                mma_f16(acc[mi][nj],
                        reinterpret_cast<const uint32_t*>(&a[mi]),
                        reinterpret_cast<const uint32_t*>(&b[nj]));
    }

    // ---- C dump (64 x 64, scalar stores, odd pitch) ----
    {
        const int g = lane >> 2, t = lane & 3;
        #pragma unroll
        for (int mi = 0; mi < 2; mi++)
            #pragma unroll
            for (int nj = 0; nj < 4; nj++) {
                int r = m_sel * 32 + 16 * mi + g;
                int c = n_sel * 32 + 8 * nj + 2 * t;
                Cs[r * CP + c]           = acc[mi][nj][0];
                Cs[r * CP + c + 1]       = acc[mi][nj][1];
                Cs[(r + 8) * CP + c]     = acc[mi][nj][2];
                Cs[(r + 8) * CP + c + 1] = acc[mi][nj][3];
            }
    }
    __syncthreads();

    // ---- fused epilogue: 16 classes x 8 b-threads, 8 b-values each ----
    const int cc = tid & 15, bb = tid >> 4;
    const int cg = blockIdx.x * 16 + cc;
    if (cg < C_N) {
        float inv[4], Gm[16];
        #pragma unroll
        for (int s = 0; s < 4; s++) inv[s] = g_invn[cg * 4 + s];
        #pragma unroll
        for (int t = 0; t < 16; t++) Gm[t] = g_G[cg * 16 + t];
        #pragma unroll
        for (int i = 0; i < 8; i++) {
            int b = bb + 8 * i;
            float l[4];
            #pragma unroll
            for (int s = 0; s < 4; s++)
                l[s] = Cs[(4 * cc + s) * CP + b] * inv[s];
            float num = l[0]*l[0] + l[1]*l[1] + l[2]*l[2] + l[3]*l[3];
            float den2 = 0.f;
            #pragma unroll
            for (int s = 0; s < 4; s++)
                #pragma unroll
                for (int t = 0; t < 4; t++)
                    den2 += l[s] * l[t] * Gm[s * 4 + t];
            out[(size_t)(b0 + b) * C_N + cg] =
                num / fmaxf(sqrtf(fmaxf(den2, 0.f)), 1e-12f);
        }
    }
}

// ---------------------------------------------------------------------------
extern "C" void kernel_launch(void* const* d_in, const int* in_sizes, int n_in,
                              void* d_out, int out_size) {
    const float* x = (const float*)d_in[0];   // [256, 512]
    const float* W = (const float*)d_in[1];   // [1000, 4, 512]
    float* out = (float*)d_out;               // [256, 1000]

    prep_kernel<<<282, 256>>>(x, W);
    gemm_epi_kernel<<<dim3(63, 4), 128>>>(out);
}